// round 3
// baseline (speedup 1.0000x reference)
#include <cuda_runtime.h>
#include <math.h>

// Problem shape (fixed for this bench)
#define T_STEPS 64
#define BATCH   1024
#define HID     512
#define VOCAB   512
#define G4H     2048   // 4*HID

// ---------------- scratch state (allocation-free: __device__ globals) --------
__device__ __align__(16) float g_x[BATCH * HID];      // current input embedding
__device__ __align__(16) float g_h[BATCH * HID];      // hidden state
__device__ __align__(16) float g_c[BATCH * HID];      // cell state
__device__ __align__(16) float g_gates[BATCH * G4H];  // pre-activation gates

// ---------------- init: x = embedding[SOS=0], h = enc_h, c = enc_c ----------
__global__ void init_state(const float* __restrict__ emb,
                           const float* __restrict__ enc_h,
                           const float* __restrict__ enc_c)
{
    int idx = blockIdx.x * blockDim.x + threadIdx.x;   // [0, BATCH*HID)
    int j = idx & (HID - 1);
    g_x[idx] = emb[j];          // SOS row 0
    g_h[idx] = enc_h[idx];
    g_c[idx] = enc_c[idx];
}

// ---------------- gates GEMM: gates = x@W_ih^T + h@W_hh^T + (b_ih+b_hh) -----
// M=1024, N=2048, K=512 (twice). Tiles 128x128x16, 256 threads, 8x8 microtile.
__global__ __launch_bounds__(256, 2)
void gates_gemm(const float* __restrict__ W_ih, const float* __restrict__ W_hh,
                const float* __restrict__ b_ih, const float* __restrict__ b_hh)
{
    const int BM = 128, BN = 128, BK = 16;
    __shared__ float As[BK][BM];
    __shared__ float Bs[BK][BN];

    int tid = threadIdx.x;
    int tx = tid & 15;          // 0..15 -> N
    int ty = tid >> 4;          // 0..15 -> M
    int m0 = blockIdx.y * BM;
    int n0 = blockIdx.x * BN;

    float acc[8][8];
#pragma unroll
    for (int i = 0; i < 8; i++)
#pragma unroll
        for (int j = 0; j < 8; j++) acc[i][j] = 0.f;

#pragma unroll 1
    for (int half = 0; half < 2; half++) {
        const float* A = half ? g_h : g_x;             // [1024, 512]
        const float* W = half ? W_hh : W_ih;           // [2048, 512]
#pragma unroll 1
        for (int k0 = 0; k0 < HID; k0 += BK) {
            // load 128x16 tiles of A and W (transposed into smem)
#pragma unroll
            for (int i = 0; i < 2; i++) {
                int lid = tid + i * 256;               // 0..511
                int row = lid >> 2;                    // 0..127
                int cv  = (lid & 3) * 4;               // 0,4,8,12
                float4 va = *(const float4*)&A[(size_t)(m0 + row) * HID + k0 + cv];
                As[cv + 0][row] = va.x; As[cv + 1][row] = va.y;
                As[cv + 2][row] = va.z; As[cv + 3][row] = va.w;
                float4 vb = *(const float4*)&W[(size_t)(n0 + row) * HID + k0 + cv];
                Bs[cv + 0][row] = vb.x; Bs[cv + 1][row] = vb.y;
                Bs[cv + 2][row] = vb.z; Bs[cv + 3][row] = vb.w;
            }
            __syncthreads();
#pragma unroll
            for (int k = 0; k < BK; k++) {
                float a[8], b[8];
                *(float4*)&a[0] = *(const float4*)&As[k][ty * 8];
                *(float4*)&a[4] = *(const float4*)&As[k][ty * 8 + 4];
                *(float4*)&b[0] = *(const float4*)&Bs[k][tx * 8];
                *(float4*)&b[4] = *(const float4*)&Bs[k][tx * 8 + 4];
#pragma unroll
                for (int i = 0; i < 8; i++)
#pragma unroll
                    for (int j = 0; j < 8; j++)
                        acc[i][j] = fmaf(a[i], b[j], acc[i][j]);
            }
            __syncthreads();
        }
    }

    // epilogue: add combined bias, store gates
#pragma unroll
    for (int i = 0; i < 8; i++) {
        int m = m0 + ty * 8 + i;
#pragma unroll
        for (int j = 0; j < 8; j++) {
            int n = n0 + tx * 8 + j;
            g_gates[(size_t)m * G4H + n] = acc[i][j] + b_ih[n] + b_hh[n];
        }
    }
}

// ---------------- LSTM cell pointwise ---------------------------------------
__global__ void lstm_cell()
{
    int idx = blockIdx.x * blockDim.x + threadIdx.x;   // [0, BATCH*HID)
    int b = idx >> 9;
    int j = idx & (HID - 1);
    const float* g = g_gates + (size_t)b * G4H;
    float gi = g[j];
    float gf = g[j + 512];
    float gg = g[j + 1024];
    float go = g[j + 1536];
    float i_s = 1.f / (1.f + expf(-gi));
    float f_s = 1.f / (1.f + expf(-gf));
    float o_s = 1.f / (1.f + expf(-go));
    float c = f_s * g_c[idx] + i_s * tanhf(gg);
    g_c[idx] = c;
    g_h[idx] = o_s * tanhf(c);
}

// ---------------- logits GEMM: logits = h@W_out^T + b_out -------------------
// M=1024, N=512, K=512. Tiles 64x64x16, 256 threads, 4x4 microtile.
__global__ __launch_bounds__(256, 4)
void logits_gemm(const float* __restrict__ W_out, const float* __restrict__ b_out,
                 float* __restrict__ out)
{
    const int BM = 64, BN = 64, BK = 16;
    __shared__ float As[BK][BM];
    __shared__ float Bs[BK][BN];

    int tid = threadIdx.x;
    int tx = tid & 15;
    int ty = tid >> 4;
    int m0 = blockIdx.y * BM;
    int n0 = blockIdx.x * BN;

    float acc[4][4];
#pragma unroll
    for (int i = 0; i < 4; i++)
#pragma unroll
        for (int j = 0; j < 4; j++) acc[i][j] = 0.f;

    int row = tid >> 2;                 // 0..63
    int cv  = (tid & 3) * 4;            // 0,4,8,12

#pragma unroll 1
    for (int k0 = 0; k0 < HID; k0 += BK) {
        float4 va = *(const float4*)&g_h[(size_t)(m0 + row) * HID + k0 + cv];
        As[cv + 0][row] = va.x; As[cv + 1][row] = va.y;
        As[cv + 2][row] = va.z; As[cv + 3][row] = va.w;
        float4 vb = *(const float4*)&W_out[(size_t)(n0 + row) * HID + k0 + cv];
        Bs[cv + 0][row] = vb.x; Bs[cv + 1][row] = vb.y;
        Bs[cv + 2][row] = vb.z; Bs[cv + 3][row] = vb.w;
        __syncthreads();
#pragma unroll
        for (int k = 0; k < BK; k++) {
            float a[4], b[4];
            *(float4*)&a[0] = *(const float4*)&As[k][ty * 4];
            *(float4*)&b[0] = *(const float4*)&Bs[k][tx * 4];
#pragma unroll
            for (int i = 0; i < 4; i++)
#pragma unroll
                for (int j = 0; j < 4; j++)
                    acc[i][j] = fmaf(a[i], b[j], acc[i][j]);
        }
        __syncthreads();
    }

#pragma unroll
    for (int i = 0; i < 4; i++) {
        int m = m0 + ty * 4 + i;
#pragma unroll
        for (int j = 0; j < 4; j++) {
            int n = n0 + tx * 4 + j;
            out[(size_t)m * VOCAB + n] = acc[i][j] + b_out[n];
        }
    }
}

// ---------------- argmax over V + embedding gather --------------------------
// one block (128 threads) per batch row; first-max tie-break to match jnp.argmax
__global__ void argmax_gather(const float* __restrict__ logits,
                              const float* __restrict__ emb)
{
    int b = blockIdx.x;
    const float* row = logits + (size_t)b * VOCAB;
    int tid = threadIdx.x;

    float best = -INFINITY;
    int bi = 0;
#pragma unroll
    for (int m = 0; m < VOCAB / 128; m++) {
        int j = tid + m * 128;
        float v = row[j];
        if (v > best) { best = v; bi = j; }   // strict > keeps earliest index
    }
    // warp reduce (prefer lower index on exact ties)
#pragma unroll
    for (int off = 16; off; off >>= 1) {
        float ov = __shfl_down_sync(0xffffffffu, best, off);
        int   oi = __shfl_down_sync(0xffffffffu, bi, off);
        if (ov > best || (ov == best && oi < bi)) { best = ov; bi = oi; }
    }
    __shared__ float sv[4];
    __shared__ int   si[4];
    __shared__ int   s_idx;
    if ((tid & 31) == 0) { sv[tid >> 5] = best; si[tid >> 5] = bi; }
    __syncthreads();
    if (tid == 0) {
        float bv = sv[0]; int bb = si[0];
#pragma unroll
        for (int w = 1; w < 4; w++)
            if (sv[w] > bv || (sv[w] == bv && si[w] < bb)) { bv = sv[w]; bb = si[w]; }
        s_idx = bb;
    }
    __syncthreads();
    int idx = s_idx;
    // gather next input embedding: 512 floats = 128 float4
    const float4* src = (const float4*)(emb + (size_t)idx * HID);
    float4* dst = (float4*)(g_x + (size_t)b * HID);
    dst[tid] = src[tid];
}

// ---------------- launch ----------------------------------------------------
extern "C" void kernel_launch(void* const* d_in, const int* in_sizes, int n_in,
                              void* d_out, int out_size)
{
    // metadata order:
    // 0 target_var(i64), 1 target_max_len, 2 encoder_hidden, 3 encoder_cell,
    // 4 embedding, 5 W_ih, 6 W_hh, 7 b_ih, 8 b_hh, 9 W_out, 10 b_out
    const float* enc_h = (const float*)d_in[2];
    const float* enc_c = (const float*)d_in[3];
    const float* emb   = (const float*)d_in[4];
    const float* W_ih  = (const float*)d_in[5];
    const float* W_hh  = (const float*)d_in[6];
    const float* b_ih  = (const float*)d_in[7];
    const float* b_hh  = (const float*)d_in[8];
    const float* W_out = (const float*)d_in[9];
    const float* b_out = (const float*)d_in[10];
    float* out = (float*)d_out;

    init_state<<<(BATCH * HID) / 256, 256>>>(emb, enc_h, enc_c);

    for (int t = 0; t < T_STEPS; t++) {
        gates_gemm<<<dim3(G4H / 128, BATCH / 128), 256>>>(W_ih, W_hh, b_ih, b_hh);
        lstm_cell<<<(BATCH * HID) / 256, 256>>>();
        float* logits_t = out + (size_t)t * BATCH * VOCAB;
        logits_gemm<<<dim3(VOCAB / 64, BATCH / 64), 256>>>(W_out, b_out, logits_t);
        argmax_gather<<<BATCH, 128>>>(logits_t, emb);
    }
}

// round 6
// speedup vs baseline: 1.2158x; 1.2158x over previous
#include <cuda_runtime.h>
#include <cuda_bf16.h>
#include <math.h>
#include <stdint.h>

#define T_STEPS 64
#define BATCH   1024
#define HID     512
#define VOCAB   512
#define G4H     2048

typedef __nv_bfloat16 bf16;

// ---------------------------------------------------------------------------
// Device-global scratch (allocation-free)
// ---------------------------------------------------------------------------
__device__ float g_c[BATCH * HID];            // cell state fp32
__device__ bf16  g_hs[2][3][BATCH * HID];     // h 3-way splits, ping-pong
__device__ bf16  g_Wih[3][G4H * HID];         // gate-interleaved W_ih splits
__device__ bf16  g_Whh[3][G4H * HID];         // gate-interleaved W_hh splits
__device__ bf16  g_Wo[3][VOCAB * HID];        // W_out splits
__device__ bf16  g_emb[3][VOCAB * HID];       // embedding splits
__device__ float g_bias[G4H];                 // gate-interleaved b_ih+b_hh
__device__ float g_E[VOCAB * G4H];            // emb @ W_ih^T + bias (fp32)
__device__ int   g_tok[BATCH];                // current token per batch lane

// ---------------------------------------------------------------------------
// Helpers
// ---------------------------------------------------------------------------
__device__ __forceinline__ uint32_t smem_u32(const void* p) {
    uint32_t a;
    asm("{ .reg .u64 t; cvta.to.shared.u64 t, %1; cvt.u32.u64 %0, t; }"
        : "=r"(a) : "l"(p));
    return a;
}

#define SWZ(x) ((x) ^ (((x) >> 3) & 0x70))

__device__ __forceinline__ void cp16(uint32_t dst, const void* src) {
    asm volatile("cp.async.cg.shared.global [%0], [%1], 16;" :: "r"(dst), "l"(src));
}

__device__ __forceinline__ void ldsm4(uint32_t& r0, uint32_t& r1,
                                      uint32_t& r2, uint32_t& r3, uint32_t addr) {
    asm volatile("ldmatrix.sync.aligned.m8n8.x4.shared.b16 {%0,%1,%2,%3}, [%4];"
                 : "=r"(r0), "=r"(r1), "=r"(r2), "=r"(r3) : "r"(addr));
}

__device__ __forceinline__ void mma_bf16(float c[4], const uint32_t a[4],
                                         const uint32_t b[2]) {
    asm volatile(
        "mma.sync.aligned.m16n8k16.row.col.f32.bf16.bf16.f32 "
        "{%0,%1,%2,%3}, {%4,%5,%6,%7}, {%8,%9}, {%0,%1,%2,%3};"
        : "+f"(c[0]), "+f"(c[1]), "+f"(c[2]), "+f"(c[3])
        : "r"(a[0]), "r"(a[1]), "r"(a[2]), "r"(a[3]), "r"(b[0]), "r"(b[1]));
}

// Exact 3-way bf16 split
__device__ __forceinline__ void split3(float v, bf16& s0, bf16& s1, bf16& s2) {
    s0 = __float2bfloat16(v);
    float r = v - __bfloat162float(s0);
    s1 = __float2bfloat16(r);
    float r2 = r - __bfloat162float(s1);
    s2 = __float2bfloat16(r2);
}

// split-product pairs (A split idx, B split idx), i+j <= 4
__device__ __constant__ int PA[6] = {0, 0, 1, 0, 1, 2};
__device__ __constant__ int PB[6] = {0, 1, 0, 2, 1, 0};

// ---------------------------------------------------------------------------
// Prep kernels
// ---------------------------------------------------------------------------
__global__ void prep_gates(const float* __restrict__ Wih, const float* __restrict__ Whh,
                           const float* __restrict__ bih, const float* __restrict__ bhh) {
    int idx = blockIdx.x * blockDim.x + threadIdx.x;    // [0, G4H*HID)
    int n = idx >> 9;
    int k = idx & 511;
    int orig = ((n & 3) << 9) + (n >> 2);               // interleave i,f,g,o per j
    split3(Wih[(size_t)orig * 512 + k], g_Wih[0][idx], g_Wih[1][idx], g_Wih[2][idx]);
    split3(Whh[(size_t)orig * 512 + k], g_Whh[0][idx], g_Whh[1][idx], g_Whh[2][idx]);
    if (k == 0) g_bias[n] = bih[orig] + bhh[orig];
}

__global__ void prep_out(const float* __restrict__ Wout, const float* __restrict__ emb) {
    int idx = blockIdx.x * blockDim.x + threadIdx.x;    // [0, VOCAB*HID)
    split3(Wout[idx], g_Wo[0][idx], g_Wo[1][idx], g_Wo[2][idx]);
    split3(emb[idx], g_emb[0][idx], g_emb[1][idx], g_emb[2][idx]);
}

__global__ void init_state_tc(const float* __restrict__ ench,
                              const float* __restrict__ encc) {
    int idx = blockIdx.x * blockDim.x + threadIdx.x;    // [0, BATCH*HID)
    g_c[idx] = encc[idx];
    split3(ench[idx], g_hs[0][0][idx], g_hs[0][1][idx], g_hs[0][2][idx]);
    if ((idx & 511) == 0) g_tok[idx >> 9] = 0;          // SOS
}

// ---------------------------------------------------------------------------
// 128x128 main loop (K=512 in 8 chunks of 64), 256 threads, 8 warps (2Mx4N)
// Warp tile 64x32.  smem: double buffer of 6 tiles x 16KB (3 A splits, 3 B).
// ---------------------------------------------------------------------------
#define TILE128   16384
#define BUF128    (6 * TILE128)        // 98304
#define SMEM128   (2 * BUF128 + 1024)

__device__ __forceinline__ void load128(uint32_t bufb, int tid,
                                        const bf16* const srcs[6], int koff) {
#pragma unroll
    for (int i = 0; i < 24; i++) {
        int u = tid + i * 256;
        int row = (u >> 3) & 127;
        int cb = u & 7;
        cp16(bufb + ((i >> 2) << 14) + SWZ(row * 128 + cb * 16),
             srcs[i >> 2] + (size_t)row * 512 + koff + cb * 8);
    }
    asm volatile("cp.async.commit_group;" ::: "memory");
}

__device__ __forceinline__ void mainloop128(uint32_t smem, int tid,
                                            const bf16* A0, const bf16* A1, const bf16* A2,
                                            const bf16* B0, const bf16* B1, const bf16* B2,
                                            float C[4][4][4]) {
    const int l = tid & 31, wid = tid >> 5;
    const int wm = wid >> 2, wn = wid & 3;
    const bf16* srcs[6] = {A0, A1, A2, B0, B1, B2};

    const int a_row = l & 15;
    const int a_cb  = (l >> 4) << 4;
    const int b_row = (((l >> 4) & 1) << 3) + (l & 7);
    const int b_cb  = ((l >> 3) & 1) << 4;

    load128(smem, tid, srcs, 0);

#pragma unroll 1
    for (int ch = 0; ch < 8; ch++) {
        uint32_t cur = smem + (ch & 1) * BUF128;
        if (ch < 7) {
            load128(smem + ((ch + 1) & 1) * BUF128, tid, srcs, (ch + 1) * 64);
            asm volatile("cp.async.wait_group 1;" ::: "memory");
        } else {
            asm volatile("cp.async.wait_group 0;" ::: "memory");
        }
        __syncthreads();

#pragma unroll
        for (int ks = 0; ks < 4; ks++) {
            uint32_t A[3][4][4];
            uint32_t B[3][4][2];
#pragma unroll
            for (int s = 0; s < 3; s++) {
#pragma unroll
                for (int mf = 0; mf < 4; mf++) {
                    uint32_t ad = cur + (s << 14) +
                        SWZ((wm * 64 + mf * 16 + a_row) * 128 + ks * 32 + a_cb);
                    ldsm4(A[s][mf][0], A[s][mf][1], A[s][mf][2], A[s][mf][3], ad);
                }
#pragma unroll
                for (int nh = 0; nh < 2; nh++) {
                    uint32_t ad = cur + 3 * TILE128 + (s << 14) +
                        SWZ((wn * 32 + nh * 16 + b_row) * 128 + ks * 32 + b_cb);
                    uint32_t r0, r1, r2, r3;
                    ldsm4(r0, r1, r2, r3, ad);
                    B[s][nh * 2][0] = r0; B[s][nh * 2][1] = r1;
                    B[s][nh * 2 + 1][0] = r2; B[s][nh * 2 + 1][1] = r3;
                }
            }
#pragma unroll
            for (int p = 0; p < 6; p++) {
#pragma unroll
                for (int mf = 0; mf < 4; mf++)
#pragma unroll
                    for (int nf = 0; nf < 4; nf++)
                        mma_bf16(C[mf][nf], A[PA[p]][mf], B[PB[p]][nf]);
            }
        }
        __syncthreads();
    }
}

// ---------------------------------------------------------------------------
// prep_E: E = emb @ W_ih^T + bias  (M=512, N=2048, K=512), grid (16, 4)
// ---------------------------------------------------------------------------
__global__ __launch_bounds__(256, 1) void prep_E_kernel() {
    extern __shared__ char dsm[];
    uint32_t smem = (smem_u32(dsm) + 1023) & ~1023u;
    int tid = threadIdx.x;
    int l = tid & 31, wid = tid >> 5;
    int wm = wid >> 2, wn = wid & 3, tg = l & 3;
    int n0 = blockIdx.x * 128, m0 = blockIdx.y * 128;

    float C[4][4][4] = {};
    mainloop128(smem, tid,
                g_emb[0] + (size_t)m0 * 512, g_emb[1] + (size_t)m0 * 512,
                g_emb[2] + (size_t)m0 * 512,
                g_Wih[0] + (size_t)n0 * 512, g_Wih[1] + (size_t)n0 * 512,
                g_Wih[2] + (size_t)n0 * 512, C);

#pragma unroll
    for (int mf = 0; mf < 4; mf++)
#pragma unroll
        for (int nf = 0; nf < 4; nf++) {
            int n = n0 + wn * 32 + nf * 8 + tg * 2;
#pragma unroll
            for (int rh = 0; rh < 2; rh++) {
                int m = m0 + wm * 64 + mf * 16 + (l >> 2) + rh * 8;
                float2 v = make_float2(C[mf][nf][rh * 2 + 0] + g_bias[n],
                                       C[mf][nf][rh * 2 + 1] + g_bias[n + 1]);
                *(float2*)&g_E[(size_t)m * G4H + n] = v;
            }
        }
}

// ---------------------------------------------------------------------------
// Gates: gates = h @ W_hh^T (+ E[token] in epilogue) -> fused LSTM cell
// grid (16 n-tiles, 8 m-tiles), 256 threads
// ---------------------------------------------------------------------------
__global__ __launch_bounds__(256, 1) void gates_tc(int rd) {
    extern __shared__ char dsm[];
    uint32_t smem = (smem_u32(dsm) + 1023) & ~1023u;
    int tid = threadIdx.x;
    int l = tid & 31, wid = tid >> 5;
    int wm = wid >> 2, wn = wid & 3, tg = l & 3;
    int n0 = blockIdx.x * 128, m0 = blockIdx.y * 128;
    int wr = rd ^ 1;

    float C[4][4][4] = {};
    mainloop128(smem, tid,
                g_hs[rd][0] + (size_t)m0 * 512, g_hs[rd][1] + (size_t)m0 * 512,
                g_hs[rd][2] + (size_t)m0 * 512,
                g_Whh[0] + (size_t)n0 * 512, g_Whh[1] + (size_t)n0 * 512,
                g_Whh[2] + (size_t)n0 * 512, C);

    // Epilogue: even-tg lane holds (i,f) pre-acts; partner (tg^1) holds (g,o).
#pragma unroll
    for (int mf = 0; mf < 4; mf++)
#pragma unroll
        for (int rh = 0; rh < 2; rh++) {
            int m = m0 + wm * 64 + mf * 16 + (l >> 2) + rh * 8;
            int tok = g_tok[m];
            const float* Erow = g_E + (size_t)tok * G4H;
#pragma unroll
            for (int nf = 0; nf < 4; nf++) {
                float own0 = C[mf][nf][rh * 2 + 0];
                float own1 = C[mf][nf][rh * 2 + 1];
                float p0 = __shfl_xor_sync(0xffffffffu, own0, 1);
                float p1 = __shfl_xor_sync(0xffffffffu, own1, 1);
                if (!(tg & 1)) {
                    int n = n0 + wn * 32 + nf * 8 + tg * 2;   // = 4*j
                    int j = n >> 2;
                    float4 e = *(const float4*)&Erow[n];
                    float gi = own0 + e.x;
                    float gf = own1 + e.y;
                    float gg = p0 + e.z;
                    float go = p1 + e.w;
                    float is = 1.f / (1.f + expf(-gi));
                    float fs = 1.f / (1.f + expf(-gf));
                    float os = 1.f / (1.f + expf(-go));
                    size_t hx = (size_t)m * HID + j;
                    float cn = fs * g_c[hx] + is * tanhf(gg);
                    g_c[hx] = cn;
                    float hn = os * tanhf(cn);
                    split3(hn, g_hs[wr][0][hx], g_hs[wr][1][hx], g_hs[wr][2][hx]);
                }
            }
        }
}

// ---------------------------------------------------------------------------
// Logits: out = h @ W_out^T + b_out.  Tile 64x64, grid (8, 16), 256 threads
// Warp tile 32x16 (2Mx4N warps).
// ---------------------------------------------------------------------------
#define TILE64   8192
#define BUF64    (6 * TILE64)          // 49152
#define SMEM64   (2 * BUF64 + 1024)

__device__ __forceinline__ void load64(uint32_t bufb, int tid,
                                       const bf16* const srcs[6], int koff) {
#pragma unroll
    for (int i = 0; i < 12; i++) {
        int u = tid + i * 256;
        int row = (u >> 3) & 63;
        int cb = u & 7;
        cp16(bufb + ((i >> 1) << 13) + SWZ(row * 128 + cb * 16),
             srcs[i >> 1] + (size_t)row * 512 + koff + cb * 8);
    }
    asm volatile("cp.async.commit_group;" ::: "memory");
}

__global__ __launch_bounds__(256, 1) void logits_tc(int ph,
                                                    const float* __restrict__ bo,
                                                    float* __restrict__ out_t) {
    extern __shared__ char dsm[];
    uint32_t smem = (smem_u32(dsm) + 1023) & ~1023u;
    int tid = threadIdx.x;
    int l = tid & 31, wid = tid >> 5;
    int wm = wid >> 2, wn = wid & 3, tg = l & 3;
    int n0 = blockIdx.x * 64, m0 = blockIdx.y * 64;

    const bf16* srcs[6] = {
        g_hs[ph][0] + (size_t)m0 * 512, g_hs[ph][1] + (size_t)m0 * 512,
        g_hs[ph][2] + (size_t)m0 * 512,
        g_Wo[0] + (size_t)n0 * 512, g_Wo[1] + (size_t)n0 * 512,
        g_Wo[2] + (size_t)n0 * 512};

    const int a_row = l & 15;
    const int a_cb  = (l >> 4) << 4;
    const int b_row = (((l >> 4) & 1) << 3) + (l & 7);
    const int b_cb  = ((l >> 3) & 1) << 4;

    float C[2][2][4] = {};

    load64(smem, tid, srcs, 0);
#pragma unroll 1
    for (int ch = 0; ch < 8; ch++) {
        uint32_t cur = smem + (ch & 1) * BUF64;
        if (ch < 7) {
            load64(smem + ((ch + 1) & 1) * BUF64, tid, srcs, (ch + 1) * 64);
            asm volatile("cp.async.wait_group 1;" ::: "memory");
        } else {
            asm volatile("cp.async.wait_group 0;" ::: "memory");
        }
        __syncthreads();

#pragma unroll
        for (int ks = 0; ks < 4; ks++) {
            uint32_t A[3][2][4];
            uint32_t B[3][2][2];
#pragma unroll
            for (int s = 0; s < 3; s++) {
#pragma unroll
                for (int mf = 0; mf < 2; mf++) {
                    uint32_t ad = cur + (s << 13) +
                        SWZ((wm * 32 + mf * 16 + a_row) * 128 + ks * 32 + a_cb);
                    ldsm4(A[s][mf][0], A[s][mf][1], A[s][mf][2], A[s][mf][3], ad);
                }
                uint32_t ad = cur + 3 * TILE64 + (s << 13) +
                    SWZ((wn * 16 + b_row) * 128 + ks * 32 + b_cb);
                uint32_t r0, r1, r2, r3;
                ldsm4(r0, r1, r2, r3, ad);
                B[s][0][0] = r0; B[s][0][1] = r1;
                B[s][1][0] = r2; B[s][1][1] = r3;
            }
#pragma unroll
            for (int p = 0; p < 6; p++) {
#pragma unroll
                for (int mf = 0; mf < 2; mf++)
#pragma unroll
                    for (int nf = 0; nf < 2; nf++)
                        mma_bf16(C[mf][nf], A[PA[p]][mf], B[PB[p]][nf]);
            }
        }
        __syncthreads();
    }

#pragma unroll
    for (int mf = 0; mf < 2; mf++)
#pragma unroll
        for (int nf = 0; nf < 2; nf++) {
            int n = n0 + wn * 16 + nf * 8 + tg * 2;
#pragma unroll
            for (int rh = 0; rh < 2; rh++) {
                int m = m0 + wm * 32 + mf * 16 + (l >> 2) + rh * 8;
                float2 v = make_float2(C[mf][nf][rh * 2 + 0] + bo[n],
                                       C[mf][nf][rh * 2 + 1] + bo[n + 1]);
                *(float2*)&out_t[(size_t)m * VOCAB + n] = v;
            }
        }
}

// ---------------------------------------------------------------------------
// Argmax (first-max tie-break, matches jnp.argmax) -> token index only
// ---------------------------------------------------------------------------
__global__ void argmax_tok(const float* __restrict__ logits_t) {
    int b = blockIdx.x;
    const float* row = logits_t + (size_t)b * VOCAB;
    int tid = threadIdx.x;

    float best = -INFINITY;
    int bi = 0;
#pragma unroll
    for (int m2 = 0; m2 < VOCAB / 128; m2++) {
        int j = tid + m2 * 128;
        float v = row[j];
        if (v > best) { best = v; bi = j; }
    }
#pragma unroll
    for (int off = 16; off; off >>= 1) {
        float ov = __shfl_down_sync(0xffffffffu, best, off);
        int   oi = __shfl_down_sync(0xffffffffu, bi, off);
        if (ov > best || (ov == best && oi < bi)) { best = ov; bi = oi; }
    }
    __shared__ float sv[4];
    __shared__ int   si[4];
    if ((tid & 31) == 0) { sv[tid >> 5] = best; si[tid >> 5] = bi; }
    __syncthreads();
    if (tid == 0) {
        float bv = sv[0]; int bb = si[0];
#pragma unroll
        for (int w = 1; w < 4; w++)
            if (sv[w] > bv || (sv[w] == bv && si[w] < bb)) { bv = sv[w]; bb = si[w]; }
        g_tok[b] = bb;
    }
}

// ---------------------------------------------------------------------------
// Launch
// ---------------------------------------------------------------------------
extern "C" void kernel_launch(void* const* d_in, const int* in_sizes, int n_in,
                              void* d_out, int out_size) {
    const float* enc_h = (const float*)d_in[2];
    const float* enc_c = (const float*)d_in[3];
    const float* emb   = (const float*)d_in[4];
    const float* W_ih  = (const float*)d_in[5];
    const float* W_hh  = (const float*)d_in[6];
    const float* b_ih  = (const float*)d_in[7];
    const float* b_hh  = (const float*)d_in[8];
    const float* W_out = (const float*)d_in[9];
    const float* b_out = (const float*)d_in[10];
    float* out = (float*)d_out;

    cudaFuncSetAttribute(prep_E_kernel, cudaFuncAttributeMaxDynamicSharedMemorySize, SMEM128);
    cudaFuncSetAttribute(gates_tc, cudaFuncAttributeMaxDynamicSharedMemorySize, SMEM128);
    cudaFuncSetAttribute(logits_tc, cudaFuncAttributeMaxDynamicSharedMemorySize, SMEM64);

    prep_gates<<<(G4H * HID) / 256, 256>>>(W_ih, W_hh, b_ih, b_hh);
    prep_out<<<(VOCAB * HID) / 256, 256>>>(W_out, emb);
    init_state_tc<<<(BATCH * HID) / 256, 256>>>(enc_h, enc_c);
    prep_E_kernel<<<dim3(16, 4), 256, SMEM128>>>();

    for (int t = 0; t < T_STEPS; t++) {
        int rd = t & 1;
        gates_tc<<<dim3(16, 8), 256, SMEM128>>>(rd);
        float* logits_t = out + (size_t)t * BATCH * VOCAB;
        logits_tc<<<dim3(8, 16), 256, SMEM64>>>(rd ^ 1, b_out, logits_t);
        argmax_tok<<<BATCH, 128>>>(logits_t);
    }
}

// round 7
// speedup vs baseline: 2.5516x; 2.0987x over previous
#include <cuda_runtime.h>
#include <cuda_bf16.h>
#include <math.h>
#include <stdint.h>

#define T_STEPS 64
#define BATCH   1024
#define HID     512
#define VOCAB   512
#define G4H     2048

typedef __nv_bfloat16 bf16;

// ---------------------------------------------------------------------------
// Device-global scratch (allocation-free)
// ---------------------------------------------------------------------------
__device__ float g_c[BATCH * HID];            // cell state fp32
__device__ bf16  g_hs[2][3][BATCH * HID];     // h 3-way splits, ping-pong
__device__ bf16  g_Wih[3][G4H * HID];         // gate-interleaved W_ih splits
__device__ bf16  g_Whh[3][G4H * HID];         // gate-interleaved W_hh splits
__device__ bf16  g_Wo[3][VOCAB * HID];        // W_out splits
__device__ bf16  g_emb[3][VOCAB * HID];       // embedding splits
__device__ float g_bias[G4H];                 // gate-interleaved b_ih+b_hh
__device__ float g_E[VOCAB * G4H];            // emb @ W_ih^T + bias (fp32)
__device__ int   g_tok[BATCH];                // current token per batch lane

// ---------------------------------------------------------------------------
// Helpers
// ---------------------------------------------------------------------------
__device__ __forceinline__ uint32_t smem_u32(const void* p) {
    uint32_t a;
    asm("{ .reg .u64 t; cvta.to.shared.u64 t, %1; cvt.u32.u64 %0, t; }"
        : "=r"(a) : "l"(p));
    return a;
}

#define SWZ(x) ((x) ^ (((x) >> 3) & 0x70))

__device__ __forceinline__ void cp16(uint32_t dst, const void* src) {
    asm volatile("cp.async.cg.shared.global [%0], [%1], 16;" :: "r"(dst), "l"(src));
}

__device__ __forceinline__ void ldsm4(uint32_t& r0, uint32_t& r1,
                                      uint32_t& r2, uint32_t& r3, uint32_t addr) {
    asm volatile("ldmatrix.sync.aligned.m8n8.x4.shared.b16 {%0,%1,%2,%3}, [%4];"
                 : "=r"(r0), "=r"(r1), "=r"(r2), "=r"(r3) : "r"(addr));
}

__device__ __forceinline__ void mma_bf16(float c[4], const uint32_t a[4],
                                         const uint32_t b[2]) {
    asm volatile(
        "mma.sync.aligned.m16n8k16.row.col.f32.bf16.bf16.f32 "
        "{%0,%1,%2,%3}, {%4,%5,%6,%7}, {%8,%9}, {%0,%1,%2,%3};"
        : "+f"(c[0]), "+f"(c[1]), "+f"(c[2]), "+f"(c[3])
        : "r"(a[0]), "r"(a[1]), "r"(a[2]), "r"(a[3]), "r"(b[0]), "r"(b[1]));
}

// Exact 3-way bf16 split
__device__ __forceinline__ void split3(float v, bf16& s0, bf16& s1, bf16& s2) {
    s0 = __float2bfloat16(v);
    float r = v - __bfloat162float(s0);
    s1 = __float2bfloat16(r);
    float r2 = r - __bfloat162float(s1);
    s2 = __float2bfloat16(r2);
}

// ---------------------------------------------------------------------------
// Prep kernels
// ---------------------------------------------------------------------------
__global__ void prep_gates(const float* __restrict__ Wih, const float* __restrict__ Whh,
                           const float* __restrict__ bih, const float* __restrict__ bhh) {
    int idx = blockIdx.x * blockDim.x + threadIdx.x;    // [0, G4H*HID)
    int n = idx >> 9;
    int k = idx & 511;
    int orig = ((n & 3) << 9) + (n >> 2);               // interleave i,f,g,o per j
    split3(Wih[(size_t)orig * 512 + k], g_Wih[0][idx], g_Wih[1][idx], g_Wih[2][idx]);
    split3(Whh[(size_t)orig * 512 + k], g_Whh[0][idx], g_Whh[1][idx], g_Whh[2][idx]);
    if (k == 0) g_bias[n] = bih[orig] + bhh[orig];
}

__global__ void prep_out(const float* __restrict__ Wout, const float* __restrict__ emb) {
    int idx = blockIdx.x * blockDim.x + threadIdx.x;    // [0, VOCAB*HID)
    split3(Wout[idx], g_Wo[0][idx], g_Wo[1][idx], g_Wo[2][idx]);
    split3(emb[idx], g_emb[0][idx], g_emb[1][idx], g_emb[2][idx]);
}

__global__ void init_state_tc(const float* __restrict__ ench,
                              const float* __restrict__ encc) {
    int idx = blockIdx.x * blockDim.x + threadIdx.x;    // [0, BATCH*HID)
    g_c[idx] = encc[idx];
    split3(ench[idx], g_hs[0][0][idx], g_hs[0][1][idx], g_hs[0][2][idx]);
    if ((idx & 511) == 0) g_tok[idx >> 9] = 0;          // SOS
}

// ---------------------------------------------------------------------------
// 128x128 main loop (K=512 in 8 chunks of 64), 256 threads, 8 warps (2Mx4N)
// Warp tile 64x32.  smem: double buffer of 6 tiles x 16KB (3 A splits, 3 B).
// Fragment schedule keeps ONE A-split live at a time (reg-pressure fix).
// ---------------------------------------------------------------------------
#define TILE128   16384
#define BUF128    (6 * TILE128)        // 98304
#define SMEM128   (2 * BUF128 + 1024)

__device__ __forceinline__ void load128(uint32_t bufb, int tid,
                                        const bf16* const srcs[6], int koff) {
#pragma unroll
    for (int i = 0; i < 24; i++) {
        int u = tid + i * 256;
        int row = (u >> 3) & 127;
        int cb = u & 7;
        cp16(bufb + ((i >> 2) << 14) + SWZ(row * 128 + cb * 16),
             srcs[i >> 2] + (size_t)row * 512 + koff + cb * 8);
    }
    asm volatile("cp.async.commit_group;" ::: "memory");
}

__device__ __forceinline__ void mainloop128(uint32_t smem, int tid,
                                            const bf16* A0, const bf16* A1, const bf16* A2,
                                            const bf16* B0, const bf16* B1, const bf16* B2,
                                            float C[4][4][4]) {
    const int l = tid & 31, wid = tid >> 5;
    const int wm = wid >> 2, wn = wid & 3;
    const bf16* srcs[6] = {A0, A1, A2, B0, B1, B2};

    const int a_row = l & 15;
    const int a_cb  = (l >> 4) << 4;
    const int b_row = (((l >> 4) & 1) << 3) + (l & 7);
    const int b_cb  = ((l >> 3) & 1) << 4;

    load128(smem, tid, srcs, 0);

#pragma unroll 1
    for (int ch = 0; ch < 8; ch++) {
        uint32_t cur = smem + (ch & 1) * BUF128;
        if (ch < 7) {
            load128(smem + ((ch + 1) & 1) * BUF128, tid, srcs, (ch + 1) * 64);
            asm volatile("cp.async.wait_group 1;" ::: "memory");
        } else {
            asm volatile("cp.async.wait_group 0;" ::: "memory");
        }
        __syncthreads();

#pragma unroll
        for (int ks = 0; ks < 4; ks++) {
            // B fragments for all 3 splits: 24 regs, stays live
            uint32_t B[3][4][2];
#pragma unroll
            for (int s = 0; s < 3; s++) {
#pragma unroll
                for (int nh = 0; nh < 2; nh++) {
                    uint32_t ad = cur + 3 * TILE128 + (s << 14) +
                        SWZ((wn * 32 + nh * 16 + b_row) * 128 + ks * 32 + b_cb);
                    uint32_t r0, r1, r2, r3;
                    ldsm4(r0, r1, r2, r3, ad);
                    B[s][nh * 2][0] = r0; B[s][nh * 2][1] = r1;
                    B[s][nh * 2 + 1][0] = r2; B[s][nh * 2 + 1][1] = r3;
                }
            }
            // One A-split live at a time; fire its allowed products (sa+sb<=2)
#pragma unroll
            for (int sa = 0; sa < 3; sa++) {
                uint32_t A[4][4];
#pragma unroll
                for (int mf = 0; mf < 4; mf++) {
                    uint32_t ad = cur + (sa << 14) +
                        SWZ((wm * 64 + mf * 16 + a_row) * 128 + ks * 32 + a_cb);
                    ldsm4(A[mf][0], A[mf][1], A[mf][2], A[mf][3], ad);
                }
#pragma unroll
                for (int sb = 0; sb < 3 - sa; sb++) {
#pragma unroll
                    for (int mf = 0; mf < 4; mf++)
#pragma unroll
                        for (int nf = 0; nf < 4; nf++)
                            mma_bf16(C[mf][nf], A[mf], B[sb][nf]);
                }
            }
        }
        __syncthreads();
    }
}

// ---------------------------------------------------------------------------
// prep_E: E = emb @ W_ih^T + bias  (M=512, N=2048, K=512), grid (16, 4)
// ---------------------------------------------------------------------------
__global__ __launch_bounds__(256, 1) void prep_E_kernel() {
    extern __shared__ char dsm[];
    uint32_t smem = (smem_u32(dsm) + 1023) & ~1023u;
    int tid = threadIdx.x;
    int l = tid & 31, wid = tid >> 5;
    int wm = wid >> 2, wn = wid & 3, tg = l & 3;
    int n0 = blockIdx.x * 128, m0 = blockIdx.y * 128;

    float C[4][4][4] = {};
    mainloop128(smem, tid,
                g_emb[0] + (size_t)m0 * 512, g_emb[1] + (size_t)m0 * 512,
                g_emb[2] + (size_t)m0 * 512,
                g_Wih[0] + (size_t)n0 * 512, g_Wih[1] + (size_t)n0 * 512,
                g_Wih[2] + (size_t)n0 * 512, C);

#pragma unroll
    for (int mf = 0; mf < 4; mf++)
#pragma unroll
        for (int nf = 0; nf < 4; nf++) {
            int n = n0 + wn * 32 + nf * 8 + tg * 2;
#pragma unroll
            for (int rh = 0; rh < 2; rh++) {
                int m = m0 + wm * 64 + mf * 16 + (l >> 2) + rh * 8;
                float2 v = make_float2(C[mf][nf][rh * 2 + 0] + g_bias[n],
                                       C[mf][nf][rh * 2 + 1] + g_bias[n + 1]);
                *(float2*)&g_E[(size_t)m * G4H + n] = v;
            }
        }
}

// ---------------------------------------------------------------------------
// Gates: gates = h @ W_hh^T (+ E[token] in epilogue) -> fused LSTM cell
// grid (16 n-tiles, 8 m-tiles), 256 threads
// ---------------------------------------------------------------------------
__global__ __launch_bounds__(256, 1) void gates_tc(int rd) {
    extern __shared__ char dsm[];
    uint32_t smem = (smem_u32(dsm) + 1023) & ~1023u;
    int tid = threadIdx.x;
    int l = tid & 31, wid = tid >> 5;
    int wm = wid >> 2, wn = wid & 3, tg = l & 3;
    int n0 = blockIdx.x * 128, m0 = blockIdx.y * 128;
    int wr = rd ^ 1;

    float C[4][4][4] = {};
    mainloop128(smem, tid,
                g_hs[rd][0] + (size_t)m0 * 512, g_hs[rd][1] + (size_t)m0 * 512,
                g_hs[rd][2] + (size_t)m0 * 512,
                g_Whh[0] + (size_t)n0 * 512, g_Whh[1] + (size_t)n0 * 512,
                g_Whh[2] + (size_t)n0 * 512, C);

    // Epilogue: even-tg lane holds (i,f) pre-acts; partner (tg^1) holds (g,o).
#pragma unroll
    for (int mf = 0; mf < 4; mf++)
#pragma unroll
        for (int rh = 0; rh < 2; rh++) {
            int m = m0 + wm * 64 + mf * 16 + (l >> 2) + rh * 8;
            int tok = g_tok[m];
            const float* Erow = g_E + (size_t)tok * G4H;
#pragma unroll
            for (int nf = 0; nf < 4; nf++) {
                float own0 = C[mf][nf][rh * 2 + 0];
                float own1 = C[mf][nf][rh * 2 + 1];
                float p0 = __shfl_xor_sync(0xffffffffu, own0, 1);
                float p1 = __shfl_xor_sync(0xffffffffu, own1, 1);
                if (!(tg & 1)) {
                    int n = n0 + wn * 32 + nf * 8 + tg * 2;   // = 4*j
                    int j = n >> 2;
                    float4 e = *(const float4*)&Erow[n];
                    float gi = own0 + e.x;
                    float gf = own1 + e.y;
                    float gg = p0 + e.z;
                    float go = p1 + e.w;
                    float is = 1.f / (1.f + expf(-gi));
                    float fs = 1.f / (1.f + expf(-gf));
                    float os = 1.f / (1.f + expf(-go));
                    size_t hx = (size_t)m * HID + j;
                    float cn = fs * g_c[hx] + is * tanhf(gg);
                    g_c[hx] = cn;
                    float hn = os * tanhf(cn);
                    split3(hn, g_hs[wr][0][hx], g_hs[wr][1][hx], g_hs[wr][2][hx]);
                }
            }
        }
}

// ---------------------------------------------------------------------------
// Logits: out = h @ W_out^T + b_out.  Tile 64x64, grid (8, 16), 256 threads
// Warp tile 32x16 (2Mx4N warps).
// ---------------------------------------------------------------------------
#define TILE64   8192
#define BUF64    (6 * TILE64)          // 49152
#define SMEM64   (2 * BUF64 + 1024)

__device__ __forceinline__ void load64(uint32_t bufb, int tid,
                                       const bf16* const srcs[6], int koff) {
#pragma unroll
    for (int i = 0; i < 12; i++) {
        int u = tid + i * 256;
        int row = (u >> 3) & 63;
        int cb = u & 7;
        cp16(bufb + ((i >> 1) << 13) + SWZ(row * 128 + cb * 16),
             srcs[i >> 1] + (size_t)row * 512 + koff + cb * 8);
    }
    asm volatile("cp.async.commit_group;" ::: "memory");
}

__global__ __launch_bounds__(256, 1) void logits_tc(int ph,
                                                    const float* __restrict__ bo,
                                                    float* __restrict__ out_t) {
    extern __shared__ char dsm[];
    uint32_t smem = (smem_u32(dsm) + 1023) & ~1023u;
    int tid = threadIdx.x;
    int l = tid & 31, wid = tid >> 5;
    int wm = wid >> 2, wn = wid & 3, tg = l & 3;
    int n0 = blockIdx.x * 64, m0 = blockIdx.y * 64;

    const bf16* srcs[6] = {
        g_hs[ph][0] + (size_t)m0 * 512, g_hs[ph][1] + (size_t)m0 * 512,
        g_hs[ph][2] + (size_t)m0 * 512,
        g_Wo[0] + (size_t)n0 * 512, g_Wo[1] + (size_t)n0 * 512,
        g_Wo[2] + (size_t)n0 * 512};

    const int a_row = l & 15;
    const int a_cb  = (l >> 4) << 4;
    const int b_row = (((l >> 4) & 1) << 3) + (l & 7);
    const int b_cb  = ((l >> 3) & 1) << 4;

    float C[2][2][4] = {};

    load64(smem, tid, srcs, 0);
#pragma unroll 1
    for (int ch = 0; ch < 8; ch++) {
        uint32_t cur = smem + (ch & 1) * BUF64;
        if (ch < 7) {
            load64(smem + ((ch + 1) & 1) * BUF64, tid, srcs, (ch + 1) * 64);
            asm volatile("cp.async.wait_group 1;" ::: "memory");
        } else {
            asm volatile("cp.async.wait_group 0;" ::: "memory");
        }
        __syncthreads();

#pragma unroll
        for (int ks = 0; ks < 4; ks++) {
            uint32_t B[3][2][2];
#pragma unroll
            for (int s = 0; s < 3; s++) {
                uint32_t ad = cur + 3 * TILE64 + (s << 13) +
                    SWZ((wn * 16 + b_row) * 128 + ks * 32 + b_cb);
                uint32_t r0, r1, r2, r3;
                ldsm4(r0, r1, r2, r3, ad);
                B[s][0][0] = r0; B[s][0][1] = r1;
                B[s][1][0] = r2; B[s][1][1] = r3;
            }
#pragma unroll
            for (int sa = 0; sa < 3; sa++) {
                uint32_t A[2][4];
#pragma unroll
                for (int mf = 0; mf < 2; mf++) {
                    uint32_t ad = cur + (sa << 13) +
                        SWZ((wm * 32 + mf * 16 + a_row) * 128 + ks * 32 + a_cb);
                    ldsm4(A[mf][0], A[mf][1], A[mf][2], A[mf][3], ad);
                }
#pragma unroll
                for (int sb = 0; sb < 3 - sa; sb++) {
#pragma unroll
                    for (int mf = 0; mf < 2; mf++)
#pragma unroll
                        for (int nf = 0; nf < 2; nf++)
                            mma_bf16(C[mf][nf], A[mf], B[sb][nf]);
                }
            }
        }
        __syncthreads();
    }

#pragma unroll
    for (int mf = 0; mf < 2; mf++)
#pragma unroll
        for (int nf = 0; nf < 2; nf++) {
            int n = n0 + wn * 16 + nf * 8 + tg * 2;
#pragma unroll
            for (int rh = 0; rh < 2; rh++) {
                int m = m0 + wm * 32 + mf * 16 + (l >> 2) + rh * 8;
                float2 v = make_float2(C[mf][nf][rh * 2 + 0] + bo[n],
                                       C[mf][nf][rh * 2 + 1] + bo[n + 1]);
                *(float2*)&out_t[(size_t)m * VOCAB + n] = v;
            }
        }
}

// ---------------------------------------------------------------------------
// Argmax (first-max tie-break, matches jnp.argmax) -> token index only
// ---------------------------------------------------------------------------
__global__ void argmax_tok(const float* __restrict__ logits_t) {
    int b = blockIdx.x;
    const float* row = logits_t + (size_t)b * VOCAB;
    int tid = threadIdx.x;

    float best = -INFINITY;
    int bi = 0;
#pragma unroll
    for (int m2 = 0; m2 < VOCAB / 128; m2++) {
        int j = tid + m2 * 128;
        float v = row[j];
        if (v > best) { best = v; bi = j; }
    }
#pragma unroll
    for (int off = 16; off; off >>= 1) {
        float ov = __shfl_down_sync(0xffffffffu, best, off);
        int   oi = __shfl_down_sync(0xffffffffu, bi, off);
        if (ov > best || (ov == best && oi < bi)) { best = ov; bi = oi; }
    }
    __shared__ float sv[4];
    __shared__ int   si[4];
    if ((tid & 31) == 0) { sv[tid >> 5] = best; si[tid >> 5] = bi; }
    __syncthreads();
    if (tid == 0) {
        float bv = sv[0]; int bb = si[0];
#pragma unroll
        for (int w = 1; w < 4; w++)
            if (sv[w] > bv || (sv[w] == bv && si[w] < bb)) { bv = sv[w]; bb = si[w]; }
        g_tok[b] = bb;
    }
}

// ---------------------------------------------------------------------------
// Launch
// ---------------------------------------------------------------------------
extern "C" void kernel_launch(void* const* d_in, const int* in_sizes, int n_in,
                              void* d_out, int out_size) {
    const float* enc_h = (const float*)d_in[2];
    const float* enc_c = (const float*)d_in[3];
    const float* emb   = (const float*)d_in[4];
    const float* W_ih  = (const float*)d_in[5];
    const float* W_hh  = (const float*)d_in[6];
    const float* b_ih  = (const float*)d_in[7];
    const float* b_hh  = (const float*)d_in[8];
    const float* W_out = (const float*)d_in[9];
    const float* b_out = (const float*)d_in[10];
    float* out = (float*)d_out;

    cudaFuncSetAttribute(prep_E_kernel, cudaFuncAttributeMaxDynamicSharedMemorySize, SMEM128);
    cudaFuncSetAttribute(gates_tc, cudaFuncAttributeMaxDynamicSharedMemorySize, SMEM128);
    cudaFuncSetAttribute(logits_tc, cudaFuncAttributeMaxDynamicSharedMemorySize, SMEM64);

    prep_gates<<<(G4H * HID) / 256, 256>>>(W_ih, W_hh, b_ih, b_hh);
    prep_out<<<(VOCAB * HID) / 256, 256>>>(W_out, emb);
    init_state_tc<<<(BATCH * HID) / 256, 256>>>(enc_h, enc_c);
    prep_E_kernel<<<dim3(16, 4), 256, SMEM128>>>();

    for (int t = 0; t < T_STEPS; t++) {
        int rd = t & 1;
        gates_tc<<<dim3(16, 8), 256, SMEM128>>>(rd);
        float* logits_t = out + (size_t)t * BATCH * VOCAB;
        logits_tc<<<dim3(8, 16), 256, SMEM64>>>(rd ^ 1, b_out, logits_t);
        argmax_tok<<<BATCH, 128>>>(logits_t);
    }
}